// round 13
// baseline (speedup 1.0000x reference)
#include <cuda_runtime.h>
#include <math.h>
#include <stdint.h>

#define BB 128
#define TT 512
#define DD 1024
#define HH 1024
#define NGATE 4096   // 4*H
#define NCTA 128     // persistent grid size (1/SM, all co-resident)
#define NSPLIT 8     // k-splits in recurrence

// Smem row strides (words). Both == 8 (mod 32) -> conflict-free LDS.64
// fragment reads (bank-pair = 8*gq + 2*cq is bijective per 16-lane phase).
#define LDK32  40    // rows of k-width 32 (A stages, xgates B stages)
#define LDK128 136   // rows of k-width 128 (recurrence persistent Wh slice)

// k-permutation within each 8-group: logical k -> physical pos
// p(k) = (k & ~7) | ((k & 3) << 1) | ((k >> 2) & 1)
// => physical pairs (2i, 2i+1) hold logical (i, i+4): one LDS.64 per fragment pair.
__device__ __host__ __forceinline__ int perm8(int k)
{
    return (k & ~7) | ((k & 3) << 1) | ((k >> 2) & 1);
}

// Scratch (static device globals — no runtime allocation).
__device__ float    g_xg[(size_t)TT * BB * NGATE];     // [t][b][4H] input projections (f32)
__device__ float    g_part[NSPLIT * BB * NGATE];       // split-K partials (f32)
__device__ uint32_t g_h[BB * HH];                      // recurrent h (tf32 bits, k-permuted)
__device__ uint32_t g_xtf[(size_t)BB * TT * DD];       // x tf32 bits [b][t][k-perm]
__device__ uint32_t g_wxt[4 * HH * DD];                // Wx tf32 bits TRANSPOSED [g][h][k-perm]
__device__ uint32_t g_wht[4 * HH * HH];                // Wh tf32 bits TRANSPOSED [g][h][k-perm]
__device__ unsigned g_bar;                             // grid barrier counter

__device__ __forceinline__ uint32_t f2tf32(float f)
{
    uint32_t u;
    asm("cvt.rna.tf32.f32 %0, %1;" : "=r"(u) : "f"(f));
    return u;
}

__device__ __forceinline__ void mma_tf32(float* d, const uint32_t* a, const uint32_t* b)
{
    asm volatile(
        "mma.sync.aligned.m16n8k8.row.col.f32.tf32.tf32.f32 "
        "{%0,%1,%2,%3},{%4,%5,%6,%7},{%8,%9},{%0,%1,%2,%3};"
        : "+f"(d[0]), "+f"(d[1]), "+f"(d[2]), "+f"(d[3])
        : "r"(a[0]), "r"(a[1]), "r"(a[2]), "r"(a[3]), "r"(b[0]), "r"(b[1]));
}

__device__ __forceinline__ void cpa16(uint32_t dst_smem, const void* src)
{
    asm volatile("cp.async.cg.shared.global [%0], [%1], 16;"
                 :: "r"(dst_smem), "l"(src));
}
__device__ __forceinline__ void cpa_commit()
{
    asm volatile("cp.async.commit_group;");
}
template <int N> __device__ __forceinline__ void cpa_wait()
{
    asm volatile("cp.async.wait_group %0;" :: "n"(N));
}

extern __shared__ uint32_t dynu[];

// ---------------------------------------------------------------------------
// cvt_perm: f32 -> tf32 bits with k-permutation (per 8-group interleave).
// Thread handles one 8-group: dst[2i,2i+1] = (src[i], src[i+4]).
// ---------------------------------------------------------------------------
__global__ __launch_bounds__(256) void cvt_perm(
    const float4* __restrict__ src, uint4* __restrict__ dst, int n8)
{
    int i = blockIdx.x * blockDim.x + threadIdx.x;
    if (i < n8) {
        float4 lo = src[2 * i];
        float4 hi = src[2 * i + 1];
        uint4 o0, o1;
        o0.x = f2tf32(lo.x); o0.y = f2tf32(hi.x);
        o0.z = f2tf32(lo.y); o0.w = f2tf32(hi.y);
        o1.x = f2tf32(lo.z); o1.y = f2tf32(hi.z);
        o1.z = f2tf32(lo.w); o1.w = f2tf32(hi.w);
        dst[2 * i]     = o0;
        dst[2 * i + 1] = o1;
    }
}

// ---------------------------------------------------------------------------
// cvt_tp_perm: [g][k][h] f32 -> [g][h][k-permuted] tf32 bits (1024x1024 per g).
// ---------------------------------------------------------------------------
__global__ __launch_bounds__(256) void cvt_tp_perm(
    const float* __restrict__ src, uint32_t* __restrict__ dst)
{
    __shared__ float tile[32][33];
    const int g  = blockIdx.z;
    const int k0 = blockIdx.x * 32;
    const int h0 = blockIdx.y * 32;
    const int tx = threadIdx.x;        // 0..31
    const int ty = threadIdx.y;        // 0..7
#pragma unroll
    for (int i = 0; i < 4; i++)
        tile[ty + i * 8][tx] = src[(size_t)g * DD * HH + (size_t)(k0 + ty + i * 8) * HH + h0 + tx];
    __syncthreads();
    const int pk = k0 + perm8(tx);     // permuted k position for logical k = k0+tx
#pragma unroll
    for (int i = 0; i < 4; i++)
        dst[(size_t)g * HH * DD + (size_t)(h0 + ty + i * 8) * DD + pk] =
            f2tf32(tile[tx][ty + i * 8]);
}

// ---------------------------------------------------------------------------
// GEMM1 (tf32): xg[t][b][n] = sum_k x[b][t][k] * Wxt[g][n][k]
// 512 thr, block 128m x 256n x 32k, warp grid 4m x 4n, warp tile 32x64.
// A [m][LDK32], B [n][LDK32] per stage, both k-permuted -> LDS.64 fragments.
// 3-stage cp.async pipeline. grid = (16 n-tiles, 512 t).
// ---------------------------------------------------------------------------
#define XGA (128 * LDK32)        // 5120 words per A stage
#define XGB (256 * LDK32)        // 10240 words per B stage

__global__ __launch_bounds__(512, 1) void gemm_xgates(float* __restrict__ out)
{
    uint32_t* Sa = dynu;                 // [3][128][LDK32]
    uint32_t* Sb = dynu + 3 * XGA;       // [3][256][LDK32]
    const uint32_t sa_base = (uint32_t)__cvta_generic_to_shared(Sa);
    const uint32_t sb_base = (uint32_t)__cvta_generic_to_shared(Sb);

    const int tid  = threadIdx.x;
    const int lane = tid & 31;
    const int wid  = tid >> 5;        // 0..15
    const int gq   = lane >> 2;
    const int cq   = lane & 3;

    const int t  = blockIdx.y;
    const int n0 = blockIdx.x * 256;
    const int gg = n0 >> 10;
    const int hb = n0 & 1023;

    const int m0w = (wid >> 2) * 32;  // 4 warps along m
    const int n0w = (wid & 3) * 64;   // 4 warps along n

    float acc[2][8][4];
#pragma unroll
    for (int i = 0; i < 2; i++)
#pragma unroll
        for (int j = 0; j < 8; j++)
#pragma unroll
            for (int e = 0; e < 4; e++) acc[i][j][e] = 0.f;

    // A copy: row am = tid>>2 (0..127), 2 of 8 16B-segs per row
    const int am  = tid >> 2;
    const int as0 = (tid & 3) * 2;
    const uint32_t* asrc = g_xtf + ((size_t)am * TT + t) * DD + as0 * 4;
    // B copy: row bn = tid>>1 (0..255), 4 of 8 16B-segs per row
    const int bn  = tid >> 1;
    const int bs0 = (tid & 1) * 4;
    const uint32_t* bsrc = g_wxt + (size_t)gg * HH * DD + (size_t)(hb + bn) * DD + bs0 * 4;

    auto copy_stage = [&](int kt) {
        int s = kt % 3;
        uint32_t da = sa_base + (uint32_t)(s * XGA + am * LDK32 + as0 * 4) * 4;
        const uint32_t* sa = asrc + kt * 32;
#pragma unroll
        for (int j = 0; j < 2; j++)
            cpa16(da + j * 16, sa + j * 4);
        uint32_t db = sb_base + (uint32_t)(s * XGB + bn * LDK32 + bs0 * 4) * 4;
        const uint32_t* sb = bsrc + kt * 32;
#pragma unroll
        for (int j = 0; j < 4; j++)
            cpa16(db + j * 16, sb + j * 4);
        cpa_commit();
    };

    copy_stage(0);
    copy_stage(1);

    for (int kt = 0; kt < 32; kt++) {
        if (kt == 31) cpa_wait<0>(); else cpa_wait<1>();
        __syncthreads();
        if (kt + 2 < 32) copy_stage(kt + 2);

        const uint32_t* Af = Sa + (kt % 3) * XGA;
        const uint32_t* Bf = Sb + (kt % 3) * XGB;
#pragma unroll
        for (int kk = 0; kk < 4; kk++) {
            const int kc = kk * 8 + 2 * cq;   // physical col of (cq, cq+4) pair
            uint32_t af[2][4], bf[8][2];
#pragma unroll
            for (int mt = 0; mt < 2; mt++) {
                int m = m0w + mt * 16 + gq;
                uint2 va = *(const uint2*)&Af[m * LDK32 + kc];
                uint2 vb = *(const uint2*)&Af[(m + 8) * LDK32 + kc];
                af[mt][0] = va.x; af[mt][1] = vb.x;
                af[mt][2] = va.y; af[mt][3] = vb.y;
            }
#pragma unroll
            for (int nt = 0; nt < 8; nt++) {
                int n = n0w + nt * 8 + gq;
                uint2 w = *(const uint2*)&Bf[n * LDK32 + kc];
                bf[nt][0] = w.x; bf[nt][1] = w.y;
            }
#pragma unroll
            for (int mt = 0; mt < 2; mt++)
#pragma unroll
                for (int nt = 0; nt < 8; nt++)
                    mma_tf32(acc[mt][nt], af[mt], bf[nt]);
        }
    }

#pragma unroll
    for (int mt = 0; mt < 2; mt++) {
        int r0 = m0w + mt * 16 + gq;
#pragma unroll
        for (int nt = 0; nt < 8; nt++) {
            int cc = n0 + n0w + nt * 8 + 2 * cq;
            float* p0 = out + ((size_t)t * BB + r0) * NGATE + cc;
            float* p1 = out + ((size_t)t * BB + r0 + 8) * NGATE + cc;
            *(float2*)p0 = make_float2(acc[mt][nt][0], acc[mt][nt][1]);
            *(float2*)p1 = make_float2(acc[mt][nt][2], acc[mt][nt][3]);
        }
    }
}

// ---------------------------------------------------------------------------
// Grid barrier: stateless generation counter.
// ---------------------------------------------------------------------------
__device__ __forceinline__ void grid_barrier()
{
    __syncthreads();
    if (threadIdx.x == 0) {
        __threadfence();
        unsigned old = atomicAdd(&g_bar, 1u);
        unsigned target = (old / NCTA + 1u) * (unsigned)NCTA;
        while (*(volatile unsigned*)&g_bar < target) { __nanosleep(32); }
        __threadfence();
    }
    __syncthreads();
}

// ---------------------------------------------------------------------------
// Persistent recurrence (tf32): 128 CTAs x 512 threads, 512 steps.
// CTA = (n-tile 0..15 width 256, k-split 0..7 width 128). Wh slice
// [n 256][k 128-perm] stride 136 persistent in smem; h (tf32 bits, permuted,
// written by activation) streamed in 4 chunks of k32 via 3-stage cp.async
// ring [m][LDK32]. LDS.64 fragments. xg activation row prefetched pre-barrier.
// ---------------------------------------------------------------------------
#define RCA (128 * LDK32)   // words per A ring stage

__global__ __launch_bounds__(512, 1) void lstm_recurrence(
    const float* __restrict__ xg, const float* __restrict__ bias,
    float* __restrict__ out)
{
    uint32_t* BsW   = dynu;                    // [256][LDK128] persistent Wh slice
    uint32_t* Aring = dynu + 256 * LDK128;     // [3][128][LDK32] h chunks
    const uint32_t ar_base = (uint32_t)__cvta_generic_to_shared(Aring);

    const int tid  = threadIdx.x;
    const int lane = tid & 31;
    const int wid  = tid >> 5;
    const int gq   = lane >> 2;
    const int cq   = lane & 3;

    const int nt = blockIdx.x & 15;     // n-tile (width 256)
    const int ks = blockIdx.x >> 4;     // k-split 0..7 (width 128)
    const int n0 = nt * 256;
    const int gg = n0 >> 10;
    const int hb = n0 & 1023;
    const int k0 = ks * 128;

    const int m0w = (wid >> 2) * 32;
    const int n0w = (wid & 3) * 64;

    // ---- preload Wh slice -> BsW[n][k-perm] (transposed, pre-permuted) ----
    for (int i = tid; i < 256 * 32; i += 512) {   // uint4 granules: 256 rows x 32
        int nr  = i >> 5;
        int nc4 = (i & 31) * 4;
        uint4 v = *(const uint4*)(g_wht + (size_t)gg * HH * DD +
                                  (size_t)(hb + nr) * DD + k0 + nc4);
        *(uint4*)&BsW[nr * LDK128 + nc4] = v;
    }

    // Activation role: batch row b = blockIdx.x, logical cols hc2 = 2*tid, +1
    const int bown = blockIdx.x;
    const int hc2  = tid * 2;
    const int hp0  = perm8(hc2);        // permuted h-store positions
    const int hp1  = perm8(hc2 + 1);
    float2 creg = make_float2(0.f, 0.f);
    float2 bb0 = *(const float2*)(bias + hc2);
    float2 bb1 = *(const float2*)(bias + 1024 + hc2);
    float2 bb2 = *(const float2*)(bias + 2048 + hc2);
    float2 bb3 = *(const float2*)(bias + 3072 + hc2);

    *(uint2*)(g_h + bown * HH + hc2) = make_uint2(0u, 0u);
    grid_barrier();

    // A copy: row am = tid>>2, 2 of 8 16B-segs per row
    const int am  = tid >> 2;
    const int as0 = (tid & 3) * 2;
    const uint32_t* hsrc = g_h + (size_t)am * HH + k0 + as0 * 4;

    for (int t = 0; t < TT; t++) {
        float acc[2][8][4];
#pragma unroll
        for (int i = 0; i < 2; i++)
#pragma unroll
            for (int j = 0; j < 8; j++)
#pragma unroll
                for (int e = 0; e < 4; e++) acc[i][j][e] = 0.f;

        auto copy_chunk = [&](int c) {
            uint32_t da = ar_base + (uint32_t)((c % 3) * RCA + am * LDK32 + as0 * 4) * 4;
            const uint32_t* src = hsrc + c * 32;
#pragma unroll
            for (int j = 0; j < 2; j++)
                cpa16(da + j * 16, src + j * 4);
            cpa_commit();
        };

        copy_chunk(0);
        copy_chunk(1);

#pragma unroll
        for (int c = 0; c < 4; c++) {
            if (c == 3) cpa_wait<0>(); else cpa_wait<1>();
            __syncthreads();
            if (c + 2 < 4) copy_chunk(c + 2);

            const uint32_t* Af = Aring + (c % 3) * RCA;
#pragma unroll
            for (int kk = 0; kk < 4; kk++) {
                const int kc  = kk * 8 + 2 * cq;
                const int kcb = c * 32 + kc;
                uint32_t af[2][4], bf[8][2];
#pragma unroll
                for (int mt = 0; mt < 2; mt++) {
                    int m = m0w + mt * 16 + gq;
                    uint2 va = *(const uint2*)&Af[m * LDK32 + kc];
                    uint2 vb = *(const uint2*)&Af[(m + 8) * LDK32 + kc];
                    af[mt][0] = va.x; af[mt][1] = vb.x;
                    af[mt][2] = va.y; af[mt][3] = vb.y;
                }
#pragma unroll
                for (int nt2 = 0; nt2 < 8; nt2++) {
                    int n = n0w + nt2 * 8 + gq;
                    uint2 w = *(const uint2*)&BsW[n * LDK128 + kcb];
                    bf[nt2][0] = w.x; bf[nt2][1] = w.y;
                }
#pragma unroll
                for (int mt = 0; mt < 2; mt++)
#pragma unroll
                    for (int nt2 = 0; nt2 < 8; nt2++)
                        mma_tf32(acc[mt][nt2], af[mt], bf[nt2]);
            }
        }

        // prefetch activation inputs (independent of the barrier)
        const float* xgb = xg + ((size_t)t * BB + bown) * NGATE;
        float2 xv[4];
#pragma unroll
        for (int gi = 0; gi < 4; gi++)
            xv[gi] = *(const float2*)(xgb + ((gi << 10) | hc2));

        // store partials
        float* pbase = g_part + (size_t)ks * (BB * NGATE);
#pragma unroll
        for (int mt = 0; mt < 2; mt++) {
            int r0 = m0w + mt * 16 + gq;
#pragma unroll
            for (int nt2 = 0; nt2 < 8; nt2++) {
                int cc = n0 + n0w + nt2 * 8 + 2 * cq;
                *(float2*)(pbase + (size_t)r0 * NGATE + cc) =
                    make_float2(acc[mt][nt2][0], acc[mt][nt2][1]);
                *(float2*)(pbase + (size_t)(r0 + 8) * NGATE + cc) =
                    make_float2(acc[mt][nt2][2], acc[mt][nt2][3]);
            }
        }

        grid_barrier();   // partials visible

        // ---- fused activation: gates = xg + bias + sum of 8 partials ----
        {
            const float* pb = g_part + (size_t)bown * NGATE;

            float gv[4][2];
#pragma unroll
            for (int gi = 0; gi < 4; gi++) {
                int n = (gi << 10) | hc2;
                float sx = xv[gi].x, sy = xv[gi].y;
#pragma unroll
                for (int s = 0; s < NSPLIT; s++) {
                    float2 q = *(const float2*)(pb + (size_t)s * (BB * NGATE) + n);
                    sx += q.x; sy += q.y;
                }
                gv[gi][0] = sx; gv[gi][1] = sy;
            }
            gv[0][0] += bb0.x; gv[0][1] += bb0.y;
            gv[1][0] += bb1.x; gv[1][1] += bb1.y;
            gv[2][0] += bb2.x; gv[2][1] += bb2.y;
            gv[3][0] += bb3.x; gv[3][1] += bb3.y;

            float hv[2];
            float* cr = (float*)&creg;
#pragma unroll
            for (int e = 0; e < 2; e++) {
                float ig = 1.f / (1.f + expf(-gv[0][e]));
                float fg = 1.f / (1.f + expf(-gv[1][e]));
                float og = 1.f / (1.f + expf(-gv[2][e]));
                float ug = tanhf(gv[3][e]);
                float c = fg * cr[e] + ig * ug;
                cr[e] = c;
                hv[e] = og * tanhf(c);
            }
            if (t == TT - 1) {
                *(float2*)(out + bown * HH + hc2) = make_float2(hv[0], hv[1]);
            } else {
                g_h[bown * HH + hp0] = f2tf32(hv[0]);
                g_h[bown * HH + hp1] = f2tf32(hv[1]);
            }
        }

        grid_barrier();   // h visible before next GEMM
    }
}

// ---------------------------------------------------------------------------
// Launch. Inputs: x[128,512,1024], adjacency (unused), Wx[4,1024,1024],
// Wh[4,1024,1024], b[4,1024]. Output: h [128,1024] f32.
// ---------------------------------------------------------------------------
extern "C" void kernel_launch(void* const* d_in, const int* in_sizes, int n_in,
                              void* d_out, int out_size)
{
    const float* x    = (const float*)d_in[0];
    const float* Wx   = (const float*)d_in[2];
    const float* Wh   = (const float*)d_in[3];
    const float* bias = (const float*)d_in[4];
    float* out = (float*)d_out;

    float *xg;
    uint32_t *xtf, *wxt, *wht;
    cudaGetSymbolAddress((void**)&xg,  g_xg);
    cudaGetSymbolAddress((void**)&xtf, g_xtf);
    cudaGetSymbolAddress((void**)&wxt, g_wxt);
    cudaGetSymbolAddress((void**)&wht, g_wht);

    const int xg_smem  = 3 * (XGA + XGB) * 4;                 // 184320 B
    const int rec_smem = (256 * LDK128 + 3 * RCA) * 4;        // 200704 B
    static int configured = 0;
    if (!configured) {
        cudaFuncSetAttribute(gemm_xgates,
                             cudaFuncAttributeMaxDynamicSharedMemorySize, xg_smem);
        cudaFuncSetAttribute(lstm_recurrence,
                             cudaFuncAttributeMaxDynamicSharedMemorySize, rec_smem);
        configured = 1;
    }

    const int nx8 = BB * TT * DD / 8;     // 8-groups in x
    cvt_perm<<<(nx8 + 255) / 256, 256>>>((const float4*)x, (uint4*)xtf, nx8);
    cvt_tp_perm<<<dim3(32, 32, 4), dim3(32, 8)>>>(Wx, wxt);
    cvt_tp_perm<<<dim3(32, 32, 4), dim3(32, 8)>>>(Wh, wht);

    gemm_xgates<<<dim3(16, 512), 512, xg_smem>>>(xg);
    lstm_recurrence<<<NCTA, 512, rec_smem>>>(xg, bias, out);
}

// round 15
// speedup vs baseline: 1.0297x; 1.0297x over previous
#include <cuda_runtime.h>
#include <math.h>
#include <stdint.h>

#define BB 128
#define TT 512
#define DD 1024
#define HH 1024
#define NGATE 4096   // 4*H
#define NCTA 128     // persistent grid size (1/SM, all co-resident)
#define NSPLIT 8     // k-splits in recurrence

#define LDN 264      // B smem row stride ([k][n], mult by cq): 264 % 32 == 8 -> conflict-free
#define LDAK 36      // A smem row stride ([m][k32], mult by gq): 36 % 32 == 4 -> conflict-free
#define LDAK64 68    // A smem row stride ([m][k64], mult by gq): 68 % 32 == 4 -> conflict-free

// Scratch (static device globals — no runtime allocation).
__device__ float    g_xg[(size_t)TT * BB * NGATE];     // [t][b][4H] input projections (f32)
__device__ float    g_part[NSPLIT * BB * NGATE];       // split-K partials (f32)
__device__ uint32_t g_h[BB * HH];                      // recurrent h (tf32 bits)
__device__ uint32_t g_xtf[(size_t)BB * TT * DD];       // x pre-converted to tf32 bits
__device__ uint32_t g_wxtf[4 * DD * HH];               // Wx tf32 bits [g][k][h]
__device__ uint32_t g_whtf[4 * HH * HH];               // Wh tf32 bits [g][k][h]
__device__ unsigned g_bar;                             // grid barrier counter

__device__ __forceinline__ uint32_t f2tf32(float f)
{
    uint32_t u;
    asm("cvt.rna.tf32.f32 %0, %1;" : "=r"(u) : "f"(f));
    return u;
}

__device__ __forceinline__ void mma_tf32(float* d, const uint32_t* a, const uint32_t* b)
{
    asm volatile(
        "mma.sync.aligned.m16n8k8.row.col.f32.tf32.tf32.f32 "
        "{%0,%1,%2,%3},{%4,%5,%6,%7},{%8,%9},{%0,%1,%2,%3};"
        : "+f"(d[0]), "+f"(d[1]), "+f"(d[2]), "+f"(d[3])
        : "r"(a[0]), "r"(a[1]), "r"(a[2]), "r"(a[3]), "r"(b[0]), "r"(b[1]));
}

__device__ __forceinline__ void cpa16(uint32_t dst_smem, const void* src)
{
    asm volatile("cp.async.cg.shared.global [%0], [%1], 16;"
                 :: "r"(dst_smem), "l"(src));
}
__device__ __forceinline__ void cpa_commit()
{
    asm volatile("cp.async.commit_group;");
}
template <int N> __device__ __forceinline__ void cpa_wait()
{
    asm volatile("cp.async.wait_group %0;" :: "n"(N));
}

extern __shared__ uint32_t dynu[];

// ---------------------------------------------------------------------------
// Pre-convert: f32 -> tf32 bits, elementwise.
// ---------------------------------------------------------------------------
__global__ __launch_bounds__(256) void cvt_tf32_arr(
    const float4* __restrict__ src, uint4* __restrict__ dst, int n4)
{
    int i = blockIdx.x * blockDim.x + threadIdx.x;
    if (i < n4) {
        float4 v = src[i];
        uint4 u;
        u.x = f2tf32(v.x); u.y = f2tf32(v.y);
        u.z = f2tf32(v.z); u.w = f2tf32(v.w);
        dst[i] = u;
    }
}

// ---------------------------------------------------------------------------
// GEMM1 (tf32) — EXACT R11 version (measured best), including B-copy units.
// xg[t][b][n] = sum_k x[b][t][k] * Wx[g][k][h]. 512 thr, block 128x256x32,
// warp grid 4m x 4n, warp tile 32x64. 3-stage cp.async pipeline.
// ---------------------------------------------------------------------------
#define XGA (128 * LDAK)        // words per A stage
#define XGB (32 * LDN)          // words per B stage

__global__ __launch_bounds__(512, 1) void gemm_xgates(float* __restrict__ out)
{
    uint32_t* Sa = dynu;                 // [3][128][LDAK]
    uint32_t* Sb = dynu + 3 * XGA;       // [3][32][LDN]
    const uint32_t sa_base = (uint32_t)__cvta_generic_to_shared(Sa);
    const uint32_t sb_base = (uint32_t)__cvta_generic_to_shared(Sb);

    const int tid  = threadIdx.x;
    const int lane = tid & 31;
    const int wid  = tid >> 5;
    const int gq   = lane >> 2;
    const int cq   = lane & 3;

    const int t  = blockIdx.y;
    const int n0 = blockIdx.x * 256;
    const int gg = n0 >> 10;
    const int hb = n0 & 1023;

    const int m0w = (wid >> 2) * 32;
    const int n0w = (wid & 3) * 64;

    float acc[2][8][4];
#pragma unroll
    for (int i = 0; i < 2; i++)
#pragma unroll
        for (int j = 0; j < 8; j++)
#pragma unroll
            for (int e = 0; e < 4; e++) acc[i][j][e] = 0.f;

    const uint32_t* Wg = g_wxtf + (size_t)gg * DD * HH + hb;

    const int am  = tid >> 2;
    const int as0 = (tid & 3) * 2;
    const uint32_t* asrc = g_xtf + ((size_t)am * TT + t) * DD + as0 * 4;
    const int bk  = tid >> 4;                 // B row (k), 0..31
    const int bs0 = (tid & 15) * 4;           // 16B-seg base: words bs0*4 .. bs0*4+15

    auto copy_stage = [&](int kt) {
        int s = kt % 3;
        uint32_t da = sa_base + (uint32_t)(s * XGA + am * LDAK + as0 * 4) * 4;
        const uint32_t* sa = asrc + kt * 32;
#pragma unroll
        for (int j = 0; j < 2; j++)
            cpa16(da + j * 16, sa + j * 4);
        uint32_t db = sb_base + (uint32_t)(s * XGB + bk * LDN + bs0 * 4) * 4;
        const uint32_t* sb = Wg + (size_t)(kt * 32 + bk) * HH + bs0 * 4;
#pragma unroll
        for (int j = 0; j < 4; j++)
            cpa16(db + j * 16, sb + j * 4);
        cpa_commit();
    };

    copy_stage(0);
    copy_stage(1);

    for (int kt = 0; kt < 32; kt++) {
        if (kt == 31) cpa_wait<0>(); else cpa_wait<1>();
        __syncthreads();
        if (kt + 2 < 32) copy_stage(kt + 2);

        const uint32_t* Af = Sa + (kt % 3) * XGA;
        const uint32_t* Bf = Sb + (kt % 3) * XGB;
#pragma unroll
        for (int kk = 0; kk < 4; kk++) {
            const int kb = kk * 8;
            uint32_t af[2][4], bf[8][2];
#pragma unroll
            for (int mt = 0; mt < 2; mt++) {
                int m = m0w + mt * 16 + gq;
                af[mt][0] = Af[m * LDAK + kb + cq];
                af[mt][1] = Af[(m + 8) * LDAK + kb + cq];
                af[mt][2] = Af[m * LDAK + kb + cq + 4];
                af[mt][3] = Af[(m + 8) * LDAK + kb + cq + 4];
            }
#pragma unroll
            for (int nt = 0; nt < 8; nt++) {
                int n = n0w + nt * 8 + gq;
                bf[nt][0] = Bf[(kb + cq) * LDN + n];
                bf[nt][1] = Bf[(kb + cq + 4) * LDN + n];
            }
#pragma unroll
            for (int mt = 0; mt < 2; mt++)
#pragma unroll
                for (int nt = 0; nt < 8; nt++)
                    mma_tf32(acc[mt][nt], af[mt], bf[nt]);
        }
    }

#pragma unroll
    for (int mt = 0; mt < 2; mt++) {
        int r0 = m0w + mt * 16 + gq;
#pragma unroll
        for (int nt = 0; nt < 8; nt++) {
            int cc = n0 + n0w + nt * 8 + 2 * cq;
            float* p0 = out + ((size_t)t * BB + r0) * NGATE + cc;
            float* p1 = out + ((size_t)t * BB + r0 + 8) * NGATE + cc;
            *(float2*)p0 = make_float2(acc[mt][nt][0], acc[mt][nt][1]);
            *(float2*)p1 = make_float2(acc[mt][nt][2], acc[mt][nt][3]);
        }
    }
}

// ---------------------------------------------------------------------------
// Grid barrier: stateless generation counter.
// ---------------------------------------------------------------------------
__device__ __forceinline__ void grid_barrier()
{
    __syncthreads();
    if (threadIdx.x == 0) {
        __threadfence();
        unsigned old = atomicAdd(&g_bar, 1u);
        unsigned target = (old / NCTA + 1u) * (unsigned)NCTA;
        while (*(volatile unsigned*)&g_bar < target) { __nanosleep(32); }
        __threadfence();
    }
    __syncthreads();
}

// ---------------------------------------------------------------------------
// Persistent recurrence (tf32): 128 CTAs x 512 threads, 512 steps.
// CTA = (n-tile 0..15 width 256, k-split 0..7 width 128). Wh slice
// [k 128][n 256] stride 264 persistent in smem; h (tf32 bits) streamed per
// step in 2 chunks of k64 via 2-stage cp.async ring [m][LDAK64] (both copies
// issued up-front; 2 syncthreads/step). Warp grid 4m x 4n, warp tile 32x64.
// xg activation row prefetched before the partial barrier.
// ---------------------------------------------------------------------------
#define RCA (128 * LDAK64)   // words per A ring stage (k64)

__global__ __launch_bounds__(512, 1) void lstm_recurrence(
    const float* __restrict__ xg, const float* __restrict__ bias,
    float* __restrict__ out)
{
    uint32_t* BsW   = dynu;                 // [128][LDN] persistent Wh slice
    uint32_t* Aring = dynu + 128 * LDN;     // [2][128][LDAK64] h chunks (bits)
    const uint32_t ar_base = (uint32_t)__cvta_generic_to_shared(Aring);

    const int tid  = threadIdx.x;
    const int lane = tid & 31;
    const int wid  = tid >> 5;
    const int gq   = lane >> 2;
    const int cq   = lane & 3;

    const int nt = blockIdx.x & 15;     // n-tile (width 256)
    const int ks = blockIdx.x >> 4;     // k-split 0..7 (width 128)
    const int n0 = nt * 256;
    const int gg = n0 >> 10;
    const int hb = n0 & 1023;
    const int k0 = ks * 128;

    const int m0w = (wid >> 2) * 32;
    const int n0w = (wid & 3) * 64;

    const uint32_t* Wg = g_whtf + (size_t)gg * HH * HH + hb;

    // ---- preload Wh slice -> BsW[k][n] (pre-converted bits), once ----
    for (int i = tid; i < 128 * 64; i += 512) {   // uint4 granules: 128k x 64
        int kr = i >> 6;
        int nc = (i & 63) * 4;
        uint4 v = *(const uint4*)(Wg + (size_t)(k0 + kr) * HH + nc);
        *(uint4*)&BsW[kr * LDN + nc] = v;
    }

    // Activation role: batch row b = blockIdx.x, cols tid*2..+1
    const int bown = blockIdx.x;
    const int hc2  = tid * 2;
    float2 creg = make_float2(0.f, 0.f);
    float2 bb0 = *(const float2*)(bias + hc2);
    float2 bb1 = *(const float2*)(bias + 1024 + hc2);
    float2 bb2 = *(const float2*)(bias + 2048 + hc2);
    float2 bb3 = *(const float2*)(bias + 3072 + hc2);

    *(uint2*)(g_h + bown * HH + hc2) = make_uint2(0u, 0u);
    grid_barrier();

    // A copy (k64 chunks): row am = tid>>2, segs as0..as0+3 of 16 per row
    const int am  = tid >> 2;
    const int as0 = (tid & 3) * 4;            // 16B-seg base; words as0*4 .. as0*4+15
    const uint32_t* hsrc = g_h + (size_t)am * HH + k0 + as0 * 4;

    for (int t = 0; t < TT; t++) {
        float acc[2][8][4];
#pragma unroll
        for (int i = 0; i < 2; i++)
#pragma unroll
            for (int j = 0; j < 8; j++)
#pragma unroll
                for (int e = 0; e < 4; e++) acc[i][j][e] = 0.f;

        // issue both k64 chunk copies up-front
#pragma unroll
        for (int c = 0; c < 2; c++) {
            uint32_t da = ar_base + (uint32_t)(c * RCA + am * LDAK64 + as0 * 4) * 4;
            const uint32_t* src = hsrc + c * 64;
#pragma unroll
            for (int j = 0; j < 4; j++)
                cpa16(da + j * 16, src + j * 4);
            cpa_commit();
        }

#pragma unroll
        for (int c = 0; c < 2; c++) {
            if (c == 0) cpa_wait<1>(); else cpa_wait<0>();
            __syncthreads();

            const uint32_t* Af = Aring + c * RCA;
#pragma unroll
            for (int kk = 0; kk < 8; kk++) {
                const int kb = kk * 8;
                const int kw = c * 64 + kb;
                uint32_t af[2][4], bf[8][2];
#pragma unroll
                for (int mt = 0; mt < 2; mt++) {
                    int m = m0w + mt * 16 + gq;
                    af[mt][0] = Af[m * LDAK64 + kb + cq];
                    af[mt][1] = Af[(m + 8) * LDAK64 + kb + cq];
                    af[mt][2] = Af[m * LDAK64 + kb + cq + 4];
                    af[mt][3] = Af[(m + 8) * LDAK64 + kb + cq + 4];
                }
#pragma unroll
                for (int nt2 = 0; nt2 < 8; nt2++) {
                    int n = n0w + nt2 * 8 + gq;
                    bf[nt2][0] = BsW[(kw + cq) * LDN + n];
                    bf[nt2][1] = BsW[(kw + cq + 4) * LDN + n];
                }
#pragma unroll
                for (int mt = 0; mt < 2; mt++)
#pragma unroll
                    for (int nt2 = 0; nt2 < 8; nt2++)
                        mma_tf32(acc[mt][nt2], af[mt], bf[nt2]);
            }
        }

        // prefetch activation xg row (independent of the barrier)
        const float* xgb = xg + ((size_t)t * BB + bown) * NGATE;
        float2 xv[4];
#pragma unroll
        for (int gi = 0; gi < 4; gi++)
            xv[gi] = *(const float2*)(xgb + ((gi << 10) | hc2));

        // store partials
        float* pbase = g_part + (size_t)ks * (BB * NGATE);
#pragma unroll
        for (int mt = 0; mt < 2; mt++) {
            int r0 = m0w + mt * 16 + gq;
#pragma unroll
            for (int nt2 = 0; nt2 < 8; nt2++) {
                int cc = n0 + n0w + nt2 * 8 + 2 * cq;
                *(float2*)(pbase + (size_t)r0 * NGATE + cc) =
                    make_float2(acc[mt][nt2][0], acc[mt][nt2][1]);
                *(float2*)(pbase + (size_t)(r0 + 8) * NGATE + cc) =
                    make_float2(acc[mt][nt2][2], acc[mt][nt2][3]);
            }
        }

        grid_barrier();   // partials visible

        // ---- fused activation: gates = xg + bias + sum of 8 partials ----
        {
            const float* pb = g_part + (size_t)bown * NGATE;

            float gv[4][2];
#pragma unroll
            for (int gi = 0; gi < 4; gi++) {
                int n = (gi << 10) | hc2;
                float sx = xv[gi].x, sy = xv[gi].y;
#pragma unroll
                for (int s = 0; s < NSPLIT; s++) {
                    float2 q = *(const float2*)(pb + (size_t)s * (BB * NGATE) + n);
                    sx += q.x; sy += q.y;
                }
                gv[gi][0] = sx; gv[gi][1] = sy;
            }
            gv[0][0] += bb0.x; gv[0][1] += bb0.y;
            gv[1][0] += bb1.x; gv[1][1] += bb1.y;
            gv[2][0] += bb2.x; gv[2][1] += bb2.y;
            gv[3][0] += bb3.x; gv[3][1] += bb3.y;

            float hv[2];
            float* cr = (float*)&creg;
#pragma unroll
            for (int e = 0; e < 2; e++) {
                float ig = 1.f / (1.f + expf(-gv[0][e]));
                float fg = 1.f / (1.f + expf(-gv[1][e]));
                float og = 1.f / (1.f + expf(-gv[2][e]));
                float ug = tanhf(gv[3][e]);
                float c = fg * cr[e] + ig * ug;
                cr[e] = c;
                hv[e] = og * tanhf(c);
            }
            if (t == TT - 1) {
                *(float2*)(out + bown * HH + hc2) = make_float2(hv[0], hv[1]);
            } else {
                *(uint2*)(g_h + bown * HH + hc2) =
                    make_uint2(f2tf32(hv[0]), f2tf32(hv[1]));
            }
        }

        grid_barrier();   // h visible before next GEMM
    }
}

// ---------------------------------------------------------------------------
// Launch. Inputs: x[128,512,1024], adjacency (unused), Wx[4,1024,1024],
// Wh[4,1024,1024], b[4,1024]. Output: h [128,1024] f32.
// ---------------------------------------------------------------------------
extern "C" void kernel_launch(void* const* d_in, const int* in_sizes, int n_in,
                              void* d_out, int out_size)
{
    const float* x    = (const float*)d_in[0];
    const float* Wx   = (const float*)d_in[2];
    const float* Wh   = (const float*)d_in[3];
    const float* bias = (const float*)d_in[4];
    float* out = (float*)d_out;

    float *xg;
    uint32_t *xtf, *wxtf, *whtf;
    cudaGetSymbolAddress((void**)&xg,   g_xg);
    cudaGetSymbolAddress((void**)&xtf,  g_xtf);
    cudaGetSymbolAddress((void**)&wxtf, g_wxtf);
    cudaGetSymbolAddress((void**)&whtf, g_whtf);

    const int xg_smem  = (3 * XGA + 3 * XGB) * 4;           // 156672 B
    const int rec_smem = (128 * LDN + 2 * RCA) * 4;         // 204800 B
    static int configured = 0;
    if (!configured) {
        cudaFuncSetAttribute(gemm_xgates,
                             cudaFuncAttributeMaxDynamicSharedMemorySize, xg_smem);
        cudaFuncSetAttribute(lstm_recurrence,
                             cudaFuncAttributeMaxDynamicSharedMemorySize, rec_smem);
        configured = 1;
    }

    const int nx4 = BB * TT * DD / 4;
    const int nw4 = 4 * DD * HH / 4;
    cvt_tf32_arr<<<(nx4 + 255) / 256, 256>>>((const float4*)x,  (uint4*)xtf,  nx4);
    cvt_tf32_arr<<<(nw4 + 255) / 256, 256>>>((const float4*)Wx, (uint4*)wxtf, nw4);
    cvt_tf32_arr<<<(nw4 + 255) / 256, 256>>>((const float4*)Wh, (uint4*)whtf, nw4);

    gemm_xgates<<<dim3(16, 512), 512, xg_smem>>>(xg);
    lstm_recurrence<<<NCTA, 512, rec_smem>>>(xg, bias, out);
}

// round 16
// speedup vs baseline: 1.0950x; 1.0634x over previous
#include <cuda_runtime.h>
#include <math.h>
#include <stdint.h>

#define BB 128
#define TT 512
#define DD 1024
#define HH 1024
#define NGATE 4096   // 4*H
#define NCTA 128     // persistent grid size (1/SM, all co-resident)
#define NSPLIT 8     // k-splits in recurrence

#define LDN 264      // B smem row stride ([k][n], mult by cq): 264 % 32 == 8 -> conflict-free
#define LDAK 36      // A smem row stride ([m][k32], mult by gq): 36 % 32 == 4 -> conflict-free

// Scratch (static device globals — no runtime allocation).
__device__ float    g_xg[(size_t)TT * BB * NGATE];     // [t][b][4H] input projections (f32)
__device__ float    g_part[NSPLIT * BB * NGATE];       // split-K partials (f32)
__device__ uint32_t g_h[BB * HH];                      // recurrent h (tf32 bits)
__device__ uint32_t g_xtf[(size_t)BB * TT * DD];       // x pre-converted to tf32 bits
__device__ uint32_t g_wxtf[4 * DD * HH];               // Wx tf32 bits [g][k][h]
__device__ uint32_t g_whtf[4 * HH * HH];               // Wh tf32 bits [g][k][h]
__device__ unsigned g_bar;                             // grid barrier counter

__device__ __forceinline__ uint32_t f2tf32(float f)
{
    uint32_t u;
    asm("cvt.rna.tf32.f32 %0, %1;" : "=r"(u) : "f"(f));
    return u;
}

__device__ __forceinline__ void mma_tf32(float* d, const uint32_t* a, const uint32_t* b)
{
    asm volatile(
        "mma.sync.aligned.m16n8k8.row.col.f32.tf32.tf32.f32 "
        "{%0,%1,%2,%3},{%4,%5,%6,%7},{%8,%9},{%0,%1,%2,%3};"
        : "+f"(d[0]), "+f"(d[1]), "+f"(d[2]), "+f"(d[3])
        : "r"(a[0]), "r"(a[1]), "r"(a[2]), "r"(a[3]), "r"(b[0]), "r"(b[1]));
}

__device__ __forceinline__ void cpa16(uint32_t dst_smem, const void* src)
{
    asm volatile("cp.async.cg.shared.global [%0], [%1], 16;"
                 :: "r"(dst_smem), "l"(src));
}
__device__ __forceinline__ void cpa_commit()
{
    asm volatile("cp.async.commit_group;");
}
template <int N> __device__ __forceinline__ void cpa_wait()
{
    asm volatile("cp.async.wait_group %0;" :: "n"(N));
}

extern __shared__ uint32_t dynu[];

// ---------------------------------------------------------------------------
// Pre-convert: f32 -> tf32 bits, elementwise.
// ---------------------------------------------------------------------------
__global__ __launch_bounds__(256) void cvt_tf32_arr(
    const float4* __restrict__ src, uint4* __restrict__ dst, int n4)
{
    int i = blockIdx.x * blockDim.x + threadIdx.x;
    if (i < n4) {
        float4 v = src[i];
        uint4 u;
        u.x = f2tf32(v.x); u.y = f2tf32(v.y);
        u.z = f2tf32(v.z); u.w = f2tf32(v.w);
        dst[i] = u;
    }
}

// ---------------------------------------------------------------------------
// GEMM1 (tf32) — EXACT R11 version (measured best).
// xg[t][b][n] = sum_k x[b][t][k] * Wx[g][k][h]. 512 thr, block 128x256x32,
// warp grid 4m x 4n, warp tile 32x64. 3-stage cp.async pipeline.
// ---------------------------------------------------------------------------
#define XGA (128 * LDAK)        // words per A stage
#define XGB (32 * LDN)          // words per B stage

__global__ __launch_bounds__(512, 1) void gemm_xgates(float* __restrict__ out)
{
    uint32_t* Sa = dynu;                 // [3][128][LDAK]
    uint32_t* Sb = dynu + 3 * XGA;       // [3][32][LDN]
    const uint32_t sa_base = (uint32_t)__cvta_generic_to_shared(Sa);
    const uint32_t sb_base = (uint32_t)__cvta_generic_to_shared(Sb);

    const int tid  = threadIdx.x;
    const int lane = tid & 31;
    const int wid  = tid >> 5;
    const int gq   = lane >> 2;
    const int cq   = lane & 3;

    const int t  = blockIdx.y;
    const int n0 = blockIdx.x * 256;
    const int gg = n0 >> 10;
    const int hb = n0 & 1023;

    const int m0w = (wid >> 2) * 32;
    const int n0w = (wid & 3) * 64;

    float acc[2][8][4];
#pragma unroll
    for (int i = 0; i < 2; i++)
#pragma unroll
        for (int j = 0; j < 8; j++)
#pragma unroll
            for (int e = 0; e < 4; e++) acc[i][j][e] = 0.f;

    const uint32_t* Wg = g_wxtf + (size_t)gg * DD * HH + hb;

    const int am  = tid >> 2;
    const int as0 = (tid & 3) * 2;
    const uint32_t* asrc = g_xtf + ((size_t)am * TT + t) * DD + as0 * 4;
    const int bk  = tid >> 4;                 // B row (k), 0..31
    const int bs0 = (tid & 15) * 4;           // word base = bs0 (16 words per thread)

    auto copy_stage = [&](int kt) {
        int s = kt % 3;
        uint32_t da = sa_base + (uint32_t)(s * XGA + am * LDAK + as0 * 4) * 4;
        const uint32_t* sa = asrc + kt * 32;
#pragma unroll
        for (int j = 0; j < 2; j++)
            cpa16(da + j * 16, sa + j * 4);
        uint32_t db = sb_base + (uint32_t)(s * XGB + bk * LDN + bs0 * 4) * 4;
        const uint32_t* sb = Wg + (size_t)(kt * 32 + bk) * HH + bs0 * 4;
#pragma unroll
        for (int j = 0; j < 4; j++)
            cpa16(db + j * 16, sb + j * 4);
        cpa_commit();
    };

    copy_stage(0);
    copy_stage(1);

    for (int kt = 0; kt < 32; kt++) {
        if (kt == 31) cpa_wait<0>(); else cpa_wait<1>();
        __syncthreads();
        if (kt + 2 < 32) copy_stage(kt + 2);

        const uint32_t* Af = Sa + (kt % 3) * XGA;
        const uint32_t* Bf = Sb + (kt % 3) * XGB;
#pragma unroll
        for (int kk = 0; kk < 4; kk++) {
            const int kb = kk * 8;
            uint32_t af[2][4], bf[8][2];
#pragma unroll
            for (int mt = 0; mt < 2; mt++) {
                int m = m0w + mt * 16 + gq;
                af[mt][0] = Af[m * LDAK + kb + cq];
                af[mt][1] = Af[(m + 8) * LDAK + kb + cq];
                af[mt][2] = Af[m * LDAK + kb + cq + 4];
                af[mt][3] = Af[(m + 8) * LDAK + kb + cq + 4];
            }
#pragma unroll
            for (int nt = 0; nt < 8; nt++) {
                int n = n0w + nt * 8 + gq;
                bf[nt][0] = Bf[(kb + cq) * LDN + n];
                bf[nt][1] = Bf[(kb + cq + 4) * LDN + n];
            }
#pragma unroll
            for (int mt = 0; mt < 2; mt++)
#pragma unroll
                for (int nt = 0; nt < 8; nt++)
                    mma_tf32(acc[mt][nt], af[mt], bf[nt]);
        }
    }

#pragma unroll
    for (int mt = 0; mt < 2; mt++) {
        int r0 = m0w + mt * 16 + gq;
#pragma unroll
        for (int nt = 0; nt < 8; nt++) {
            int cc = n0 + n0w + nt * 8 + 2 * cq;
            float* p0 = out + ((size_t)t * BB + r0) * NGATE + cc;
            float* p1 = out + ((size_t)t * BB + r0 + 8) * NGATE + cc;
            *(float2*)p0 = make_float2(acc[mt][nt][0], acc[mt][nt][1]);
            *(float2*)p1 = make_float2(acc[mt][nt][2], acc[mt][nt][3]);
        }
    }
}

// ---------------------------------------------------------------------------
// Grid barrier: atomic arrive; POLL VIA VOLATILE LOAD (no RMW serialization
// at the LTS atomic ALU), tight spin (no nanosleep wakeup quantization).
// ---------------------------------------------------------------------------
__device__ __forceinline__ void grid_barrier()
{
    __syncthreads();
    if (threadIdx.x == 0) {
        __threadfence();
        unsigned old = atomicAdd(&g_bar, 1u);
        unsigned target = (old / NCTA + 1u) * (unsigned)NCTA;
        while (*(volatile unsigned*)&g_bar < target) { }
        __threadfence();
    }
    __syncthreads();
}

// ---------------------------------------------------------------------------
// Persistent recurrence (tf32) — R11 structure: 128 CTAs x 512 threads.
// CTA = (n-tile 0..15 width 256, k-split 0..7 width 128). Wh slice
// [k 128][n 256] stride 264 persistent in smem; h streamed per step in
// 4 chunks of k32 via 3-stage cp.async ring [m][LDAK]. Warp grid 4m x 4n,
// warp tile 32x64. xg activation row prefetched before the partial barrier.
// ---------------------------------------------------------------------------
#define RCA (128 * LDAK)   // words per A ring stage

__global__ __launch_bounds__(512, 1) void lstm_recurrence(
    const float* __restrict__ xg, const float* __restrict__ bias,
    float* __restrict__ out)
{
    uint32_t* BsW   = dynu;                 // [128][LDN] persistent Wh slice
    uint32_t* Aring = dynu + 128 * LDN;     // [3][128][LDAK] h chunks (bits)
    const uint32_t ar_base = (uint32_t)__cvta_generic_to_shared(Aring);

    const int tid  = threadIdx.x;
    const int lane = tid & 31;
    const int wid  = tid >> 5;
    const int gq   = lane >> 2;
    const int cq   = lane & 3;

    const int nt = blockIdx.x & 15;     // n-tile (width 256)
    const int ks = blockIdx.x >> 4;     // k-split 0..7 (width 128)
    const int n0 = nt * 256;
    const int gg = n0 >> 10;
    const int hb = n0 & 1023;
    const int k0 = ks * 128;

    const int m0w = (wid >> 2) * 32;
    const int n0w = (wid & 3) * 64;

    const uint32_t* Wg = g_whtf + (size_t)gg * HH * HH + hb;

    // ---- preload Wh slice -> BsW[k][n] (pre-converted bits), once ----
    for (int i = tid; i < 128 * 64; i += 512) {   // uint4 granules: 128k x 64
        int kr = i >> 6;
        int nc = (i & 63) * 4;
        uint4 v = *(const uint4*)(Wg + (size_t)(k0 + kr) * HH + nc);
        *(uint4*)&BsW[kr * LDN + nc] = v;
    }

    // Activation role: batch row b = blockIdx.x, cols tid*2..+1
    const int bown = blockIdx.x;
    const int hc2  = tid * 2;
    float2 creg = make_float2(0.f, 0.f);
    float2 bb0 = *(const float2*)(bias + hc2);
    float2 bb1 = *(const float2*)(bias + 1024 + hc2);
    float2 bb2 = *(const float2*)(bias + 2048 + hc2);
    float2 bb3 = *(const float2*)(bias + 3072 + hc2);

    *(uint2*)(g_h + bown * HH + hc2) = make_uint2(0u, 0u);
    grid_barrier();

    // A copy: row am = tid>>2, segs (tid&3)*2 + j (8 x 16B per row)
    const int am  = tid >> 2;
    const int as0 = (tid & 3) * 2;
    const uint32_t* hsrc = g_h + (size_t)am * HH + k0 + as0 * 4;

    for (int t = 0; t < TT; t++) {
        float acc[2][8][4];
#pragma unroll
        for (int i = 0; i < 2; i++)
#pragma unroll
            for (int j = 0; j < 8; j++)
#pragma unroll
                for (int e = 0; e < 4; e++) acc[i][j][e] = 0.f;

        auto copy_chunk = [&](int c) {
            uint32_t da = ar_base + (uint32_t)((c % 3) * RCA + am * LDAK + as0 * 4) * 4;
            const uint32_t* src = hsrc + c * 32;
#pragma unroll
            for (int j = 0; j < 2; j++)
                cpa16(da + j * 16, src + j * 4);
            cpa_commit();
        };

        copy_chunk(0);
        copy_chunk(1);

#pragma unroll
        for (int c = 0; c < 4; c++) {
            if (c == 3) cpa_wait<0>(); else cpa_wait<1>();
            __syncthreads();
            if (c + 2 < 4) copy_chunk(c + 2);

            const uint32_t* Af = Aring + (c % 3) * RCA;
#pragma unroll
            for (int kk = 0; kk < 4; kk++) {
                const int kb = kk * 8;
                const int kw = c * 32 + kb;
                uint32_t af[2][4], bf[8][2];
#pragma unroll
                for (int mt = 0; mt < 2; mt++) {
                    int m = m0w + mt * 16 + gq;
                    af[mt][0] = Af[m * LDAK + kb + cq];
                    af[mt][1] = Af[(m + 8) * LDAK + kb + cq];
                    af[mt][2] = Af[m * LDAK + kb + cq + 4];
                    af[mt][3] = Af[(m + 8) * LDAK + kb + cq + 4];
                }
#pragma unroll
                for (int nt2 = 0; nt2 < 8; nt2++) {
                    int n = n0w + nt2 * 8 + gq;
                    bf[nt2][0] = BsW[(kw + cq) * LDN + n];
                    bf[nt2][1] = BsW[(kw + cq + 4) * LDN + n];
                }
#pragma unroll
                for (int mt = 0; mt < 2; mt++)
#pragma unroll
                    for (int nt2 = 0; nt2 < 8; nt2++)
                        mma_tf32(acc[mt][nt2], af[mt], bf[nt2]);
            }
        }

        // prefetch activation xg row (independent of the barrier)
        const float* xgb = xg + ((size_t)t * BB + bown) * NGATE;
        float2 xv[4];
#pragma unroll
        for (int gi = 0; gi < 4; gi++)
            xv[gi] = *(const float2*)(xgb + ((gi << 10) | hc2));

        // store partials
        float* pbase = g_part + (size_t)ks * (BB * NGATE);
#pragma unroll
        for (int mt = 0; mt < 2; mt++) {
            int r0 = m0w + mt * 16 + gq;
#pragma unroll
            for (int nt2 = 0; nt2 < 8; nt2++) {
                int cc = n0 + n0w + nt2 * 8 + 2 * cq;
                *(float2*)(pbase + (size_t)r0 * NGATE + cc) =
                    make_float2(acc[mt][nt2][0], acc[mt][nt2][1]);
                *(float2*)(pbase + (size_t)(r0 + 8) * NGATE + cc) =
                    make_float2(acc[mt][nt2][2], acc[mt][nt2][3]);
            }
        }

        grid_barrier();   // partials visible

        // ---- fused activation: gates = xg + bias + sum of 8 partials ----
        {
            const float* pb = g_part + (size_t)bown * NGATE;

            float gv[4][2];
#pragma unroll
            for (int gi = 0; gi < 4; gi++) {
                int n = (gi << 10) | hc2;
                float sx = xv[gi].x, sy = xv[gi].y;
#pragma unroll
                for (int s = 0; s < NSPLIT; s++) {
                    float2 q = *(const float2*)(pb + (size_t)s * (BB * NGATE) + n);
                    sx += q.x; sy += q.y;
                }
                gv[gi][0] = sx; gv[gi][1] = sy;
            }
            gv[0][0] += bb0.x; gv[0][1] += bb0.y;
            gv[1][0] += bb1.x; gv[1][1] += bb1.y;
            gv[2][0] += bb2.x; gv[2][1] += bb2.y;
            gv[3][0] += bb3.x; gv[3][1] += bb3.y;

            float hv[2];
            float* cr = (float*)&creg;
#pragma unroll
            for (int e = 0; e < 2; e++) {
                float ig = 1.f / (1.f + expf(-gv[0][e]));
                float fg = 1.f / (1.f + expf(-gv[1][e]));
                float og = 1.f / (1.f + expf(-gv[2][e]));
                float ug = tanhf(gv[3][e]);
                float c = fg * cr[e] + ig * ug;
                cr[e] = c;
                hv[e] = og * tanhf(c);
            }
            if (t == TT - 1) {
                *(float2*)(out + bown * HH + hc2) = make_float2(hv[0], hv[1]);
            } else {
                *(uint2*)(g_h + bown * HH + hc2) =
                    make_uint2(f2tf32(hv[0]), f2tf32(hv[1]));
            }
        }

        grid_barrier();   // h visible before next GEMM
    }
}

// ---------------------------------------------------------------------------
// Launch. Inputs: x[128,512,1024], adjacency (unused), Wx[4,1024,1024],
// Wh[4,1024,1024], b[4,1024]. Output: h [128,1024] f32.
// ---------------------------------------------------------------------------
extern "C" void kernel_launch(void* const* d_in, const int* in_sizes, int n_in,
                              void* d_out, int out_size)
{
    const float* x    = (const float*)d_in[0];
    const float* Wx   = (const float*)d_in[2];
    const float* Wh   = (const float*)d_in[3];
    const float* bias = (const float*)d_in[4];
    float* out = (float*)d_out;

    float *xg;
    uint32_t *xtf, *wxtf, *whtf;
    cudaGetSymbolAddress((void**)&xg,   g_xg);
    cudaGetSymbolAddress((void**)&xtf,  g_xtf);
    cudaGetSymbolAddress((void**)&wxtf, g_wxtf);
    cudaGetSymbolAddress((void**)&whtf, g_whtf);

    const int xg_smem  = (3 * XGA + 3 * XGB) * 4;           // 156672 B
    const int rec_smem = (128 * LDN + 3 * RCA) * 4;         // 190464 B
    static int configured = 0;
    if (!configured) {
        cudaFuncSetAttribute(gemm_xgates,
                             cudaFuncAttributeMaxDynamicSharedMemorySize, xg_smem);
        cudaFuncSetAttribute(lstm_recurrence,
                             cudaFuncAttributeMaxDynamicSharedMemorySize, rec_smem);
        configured = 1;
    }

    const int nx4 = BB * TT * DD / 4;
    const int nw4 = 4 * DD * HH / 4;
    cvt_tf32_arr<<<(nx4 + 255) / 256, 256>>>((const float4*)x,  (uint4*)xtf,  nx4);
    cvt_tf32_arr<<<(nw4 + 255) / 256, 256>>>((const float4*)Wx, (uint4*)wxtf, nw4);
    cvt_tf32_arr<<<(nw4 + 255) / 256, 256>>>((const float4*)Wh, (uint4*)whtf, nw4);

    gemm_xgates<<<dim3(16, 512), 512, xg_smem>>>(xg);
    lstm_recurrence<<<NCTA, 512, rec_smem>>>(xg, bias, out);
}

// round 17
// speedup vs baseline: 1.0971x; 1.0019x over previous
#include <cuda_runtime.h>
#include <math.h>
#include <stdint.h>

#define BB 128
#define TT 512
#define DD 1024
#define HH 1024
#define NGATE 4096   // 4*H
#define NCTA 128     // persistent grid size (1/SM, all co-resident)
#define NSPLIT 8     // k-splits in recurrence

#define LDN 264      // B smem row stride ([k][n], mult by cq): 264 % 32 == 8 -> conflict-free
#define LDAK 36      // A smem row stride ([m][k32], mult by gq): 36 % 32 == 4 -> conflict-free

// Scratch (static device globals — no runtime allocation).
__device__ float    g_xg[(size_t)TT * BB * NGATE];     // [t][b][4H] input projections (f32)
__device__ float    g_part[NSPLIT * BB * NGATE];       // split-K partials (f32)
__device__ uint32_t g_h[BB * HH];                      // recurrent h (tf32 bits)
__device__ uint32_t g_xtf[(size_t)BB * TT * DD];       // x pre-converted to tf32 bits
__device__ uint32_t g_wxtf[4 * DD * HH];               // Wx tf32 bits [g][k][h]
__device__ uint32_t g_whtf[4 * HH * HH];               // Wh tf32 bits [g][k][h]
__device__ unsigned g_bar;                             // grid barrier counter

__device__ __forceinline__ uint32_t f2tf32(float f)
{
    uint32_t u;
    asm("cvt.rna.tf32.f32 %0, %1;" : "=r"(u) : "f"(f));
    return u;
}

__device__ __forceinline__ void mma_tf32(float* d, const uint32_t* a, const uint32_t* b)
{
    asm volatile(
        "mma.sync.aligned.m16n8k8.row.col.f32.tf32.tf32.f32 "
        "{%0,%1,%2,%3},{%4,%5,%6,%7},{%8,%9},{%0,%1,%2,%3};"
        : "+f"(d[0]), "+f"(d[1]), "+f"(d[2]), "+f"(d[3])
        : "r"(a[0]), "r"(a[1]), "r"(a[2]), "r"(a[3]), "r"(b[0]), "r"(b[1]));
}

__device__ __forceinline__ void cpa16(uint32_t dst_smem, const void* src)
{
    asm volatile("cp.async.cg.shared.global [%0], [%1], 16;"
                 :: "r"(dst_smem), "l"(src));
}
__device__ __forceinline__ void cpa_commit()
{
    asm volatile("cp.async.commit_group;");
}
template <int N> __device__ __forceinline__ void cpa_wait()
{
    asm volatile("cp.async.wait_group %0;" :: "n"(N));
}

extern __shared__ uint32_t dynu[];

// ---------------------------------------------------------------------------
// Pre-convert: f32 -> tf32 bits, elementwise.
// ---------------------------------------------------------------------------
__global__ __launch_bounds__(256) void cvt_tf32_arr(
    const float4* __restrict__ src, uint4* __restrict__ dst, int n4)
{
    int i = blockIdx.x * blockDim.x + threadIdx.x;
    if (i < n4) {
        float4 v = src[i];
        uint4 u;
        u.x = f2tf32(v.x); u.y = f2tf32(v.y);
        u.z = f2tf32(v.z); u.w = f2tf32(v.w);
        dst[i] = u;
    }
}

// ---------------------------------------------------------------------------
// GEMM1 (tf32) — EXACT R11/R16 version (measured best).
// xg[t][b][n] = sum_k x[b][t][k] * Wx[g][k][h]. 512 thr, block 128x256x32,
// warp grid 4m x 4n, warp tile 32x64. 3-stage cp.async pipeline.
// ---------------------------------------------------------------------------
#define XGA (128 * LDAK)        // words per A stage
#define XGB (32 * LDN)          // words per B stage

__global__ __launch_bounds__(512, 1) void gemm_xgates(float* __restrict__ out)
{
    uint32_t* Sa = dynu;                 // [3][128][LDAK]
    uint32_t* Sb = dynu + 3 * XGA;       // [3][32][LDN]
    const uint32_t sa_base = (uint32_t)__cvta_generic_to_shared(Sa);
    const uint32_t sb_base = (uint32_t)__cvta_generic_to_shared(Sb);

    const int tid  = threadIdx.x;
    const int lane = tid & 31;
    const int wid  = tid >> 5;
    const int gq   = lane >> 2;
    const int cq   = lane & 3;

    const int t  = blockIdx.y;
    const int n0 = blockIdx.x * 256;
    const int gg = n0 >> 10;
    const int hb = n0 & 1023;

    const int m0w = (wid >> 2) * 32;
    const int n0w = (wid & 3) * 64;

    float acc[2][8][4];
#pragma unroll
    for (int i = 0; i < 2; i++)
#pragma unroll
        for (int j = 0; j < 8; j++)
#pragma unroll
            for (int e = 0; e < 4; e++) acc[i][j][e] = 0.f;

    const uint32_t* Wg = g_wxtf + (size_t)gg * DD * HH + hb;

    const int am  = tid >> 2;
    const int as0 = (tid & 3) * 2;
    const uint32_t* asrc = g_xtf + ((size_t)am * TT + t) * DD + as0 * 4;
    const int bk  = tid >> 4;                 // B row (k), 0..31
    const int bs0 = (tid & 15) * 4;           // 16B-seg base

    auto copy_stage = [&](int kt) {
        int s = kt % 3;
        uint32_t da = sa_base + (uint32_t)(s * XGA + am * LDAK + as0 * 4) * 4;
        const uint32_t* sa = asrc + kt * 32;
#pragma unroll
        for (int j = 0; j < 2; j++)
            cpa16(da + j * 16, sa + j * 4);
        uint32_t db = sb_base + (uint32_t)(s * XGB + bk * LDN + bs0 * 4) * 4;
        const uint32_t* sb = Wg + (size_t)(kt * 32 + bk) * HH + bs0 * 4;
#pragma unroll
        for (int j = 0; j < 4; j++)
            cpa16(db + j * 16, sb + j * 4);
        cpa_commit();
    };

    copy_stage(0);
    copy_stage(1);

    for (int kt = 0; kt < 32; kt++) {
        if (kt == 31) cpa_wait<0>(); else cpa_wait<1>();
        __syncthreads();
        if (kt + 2 < 32) copy_stage(kt + 2);

        const uint32_t* Af = Sa + (kt % 3) * XGA;
        const uint32_t* Bf = Sb + (kt % 3) * XGB;
#pragma unroll
        for (int kk = 0; kk < 4; kk++) {
            const int kb = kk * 8;
            uint32_t af[2][4], bf[8][2];
#pragma unroll
            for (int mt = 0; mt < 2; mt++) {
                int m = m0w + mt * 16 + gq;
                af[mt][0] = Af[m * LDAK + kb + cq];
                af[mt][1] = Af[(m + 8) * LDAK + kb + cq];
                af[mt][2] = Af[m * LDAK + kb + cq + 4];
                af[mt][3] = Af[(m + 8) * LDAK + kb + cq + 4];
            }
#pragma unroll
            for (int nt = 0; nt < 8; nt++) {
                int n = n0w + nt * 8 + gq;
                bf[nt][0] = Bf[(kb + cq) * LDN + n];
                bf[nt][1] = Bf[(kb + cq + 4) * LDN + n];
            }
#pragma unroll
            for (int mt = 0; mt < 2; mt++)
#pragma unroll
                for (int nt = 0; nt < 8; nt++)
                    mma_tf32(acc[mt][nt], af[mt], bf[nt]);
        }
    }

#pragma unroll
    for (int mt = 0; mt < 2; mt++) {
        int r0 = m0w + mt * 16 + gq;
#pragma unroll
        for (int nt = 0; nt < 8; nt++) {
            int cc = n0 + n0w + nt * 8 + 2 * cq;
            float* p0 = out + ((size_t)t * BB + r0) * NGATE + cc;
            float* p1 = out + ((size_t)t * BB + r0 + 8) * NGATE + cc;
            *(float2*)p0 = make_float2(acc[mt][nt][0], acc[mt][nt][1]);
            *(float2*)p1 = make_float2(acc[mt][nt][2], acc[mt][nt][3]);
        }
    }
}

// ---------------------------------------------------------------------------
// Grid barrier, two-phase scheme:
//  - first barrier of the launch: returning atomicAdd establishes the base
//    target for this launch (graph-replay safe).
//  - subsequent barriers: fire-and-forget red.global.add (no LTS return
//    serialization) + locally computed target (tgt += NCTA).
// Poll is a volatile load; fences unchanged.
// ---------------------------------------------------------------------------
__device__ __forceinline__ void red_add1(unsigned* addr)
{
    asm volatile("red.global.add.u32 [%0], 1;" :: "l"(addr) : "memory");
}

__device__ __forceinline__ void grid_barrier_first(unsigned& tgt)
{
    __syncthreads();
    if (threadIdx.x == 0) {
        __threadfence();
        unsigned old = atomicAdd(&g_bar, 1u);
        tgt = (old / NCTA + 1u) * (unsigned)NCTA;
        while (*(volatile unsigned*)&g_bar < tgt) { }
        __threadfence();
    }
    __syncthreads();
}

__device__ __forceinline__ void grid_barrier_next(unsigned& tgt)
{
    __syncthreads();
    if (threadIdx.x == 0) {
        __threadfence();
        red_add1(&g_bar);
        tgt += (unsigned)NCTA;
        while (*(volatile unsigned*)&g_bar < tgt) { }
        __threadfence();
    }
    __syncthreads();
}

// ---------------------------------------------------------------------------
// Persistent recurrence (tf32) — R11/R16 structure: 128 CTAs x 512 threads.
// CTA = (n-tile 0..15 width 256, k-split 0..7 width 128). Wh slice
// [k 128][n 256] stride 264 persistent in smem; h streamed per step in
// 4 chunks of k32 via 3-stage cp.async ring [m][LDAK]. Warp grid 4m x 4n,
// warp tile 32x64. xg activation row prefetched before the partial barrier.
// ---------------------------------------------------------------------------
#define RCA (128 * LDAK)   // words per A ring stage

__global__ __launch_bounds__(512, 1) void lstm_recurrence(
    const float* __restrict__ xg, const float* __restrict__ bias,
    float* __restrict__ out)
{
    uint32_t* BsW   = dynu;                 // [128][LDN] persistent Wh slice
    uint32_t* Aring = dynu + 128 * LDN;     // [3][128][LDAK] h chunks (bits)
    const uint32_t ar_base = (uint32_t)__cvta_generic_to_shared(Aring);

    const int tid  = threadIdx.x;
    const int lane = tid & 31;
    const int wid  = tid >> 5;
    const int gq   = lane >> 2;
    const int cq   = lane & 3;

    const int nt = blockIdx.x & 15;     // n-tile (width 256)
    const int ks = blockIdx.x >> 4;     // k-split 0..7 (width 128)
    const int n0 = nt * 256;
    const int gg = n0 >> 10;
    const int hb = n0 & 1023;
    const int k0 = ks * 128;

    const int m0w = (wid >> 2) * 32;
    const int n0w = (wid & 3) * 64;

    const uint32_t* Wg = g_whtf + (size_t)gg * HH * HH + hb;

    // ---- preload Wh slice -> BsW[k][n] (pre-converted bits), once ----
    for (int i = tid; i < 128 * 64; i += 512) {   // uint4 granules: 128k x 64
        int kr = i >> 6;
        int nc = (i & 63) * 4;
        uint4 v = *(const uint4*)(Wg + (size_t)(k0 + kr) * HH + nc);
        *(uint4*)&BsW[kr * LDN + nc] = v;
    }

    // Activation role: batch row b = blockIdx.x, cols tid*2..+1
    const int bown = blockIdx.x;
    const int hc2  = tid * 2;
    float2 creg = make_float2(0.f, 0.f);
    float2 bb0 = *(const float2*)(bias + hc2);
    float2 bb1 = *(const float2*)(bias + 1024 + hc2);
    float2 bb2 = *(const float2*)(bias + 2048 + hc2);
    float2 bb3 = *(const float2*)(bias + 3072 + hc2);

    *(uint2*)(g_h + bown * HH + hc2) = make_uint2(0u, 0u);

    unsigned bar_tgt = 0;               // thread 0's barrier target (others unused)
    grid_barrier_first(bar_tgt);

    // A copy: row am = tid>>2, segs (tid&3)*2 + j (8 x 16B per row)
    const int am  = tid >> 2;
    const int as0 = (tid & 3) * 2;
    const uint32_t* hsrc = g_h + (size_t)am * HH + k0 + as0 * 4;

    for (int t = 0; t < TT; t++) {
        float acc[2][8][4];
#pragma unroll
        for (int i = 0; i < 2; i++)
#pragma unroll
            for (int j = 0; j < 8; j++)
#pragma unroll
                for (int e = 0; e < 4; e++) acc[i][j][e] = 0.f;

        auto copy_chunk = [&](int c) {
            uint32_t da = ar_base + (uint32_t)((c % 3) * RCA + am * LDAK + as0 * 4) * 4;
            const uint32_t* src = hsrc + c * 32;
#pragma unroll
            for (int j = 0; j < 2; j++)
                cpa16(da + j * 16, src + j * 4);
            cpa_commit();
        };

        copy_chunk(0);
        copy_chunk(1);

#pragma unroll
        for (int c = 0; c < 4; c++) {
            if (c == 3) cpa_wait<0>(); else cpa_wait<1>();
            __syncthreads();
            if (c + 2 < 4) copy_chunk(c + 2);

            const uint32_t* Af = Aring + (c % 3) * RCA;
#pragma unroll
            for (int kk = 0; kk < 4; kk++) {
                const int kb = kk * 8;
                const int kw = c * 32 + kb;
                uint32_t af[2][4], bf[8][2];
#pragma unroll
                for (int mt = 0; mt < 2; mt++) {
                    int m = m0w + mt * 16 + gq;
                    af[mt][0] = Af[m * LDAK + kb + cq];
                    af[mt][1] = Af[(m + 8) * LDAK + kb + cq];
                    af[mt][2] = Af[m * LDAK + kb + cq + 4];
                    af[mt][3] = Af[(m + 8) * LDAK + kb + cq + 4];
                }
#pragma unroll
                for (int nt2 = 0; nt2 < 8; nt2++) {
                    int n = n0w + nt2 * 8 + gq;
                    bf[nt2][0] = BsW[(kw + cq) * LDN + n];
                    bf[nt2][1] = BsW[(kw + cq + 4) * LDN + n];
                }
#pragma unroll
                for (int mt = 0; mt < 2; mt++)
#pragma unroll
                    for (int nt2 = 0; nt2 < 8; nt2++)
                        mma_tf32(acc[mt][nt2], af[mt], bf[nt2]);
            }
        }

        // prefetch activation xg row (independent of the barrier)
        const float* xgb = xg + ((size_t)t * BB + bown) * NGATE;
        float2 xv[4];
#pragma unroll
        for (int gi = 0; gi < 4; gi++)
            xv[gi] = *(const float2*)(xgb + ((gi << 10) | hc2));

        // store partials
        float* pbase = g_part + (size_t)ks * (BB * NGATE);
#pragma unroll
        for (int mt = 0; mt < 2; mt++) {
            int r0 = m0w + mt * 16 + gq;
#pragma unroll
            for (int nt2 = 0; nt2 < 8; nt2++) {
                int cc = n0 + n0w + nt2 * 8 + 2 * cq;
                *(float2*)(pbase + (size_t)r0 * NGATE + cc) =
                    make_float2(acc[mt][nt2][0], acc[mt][nt2][1]);
                *(float2*)(pbase + (size_t)(r0 + 8) * NGATE + cc) =
                    make_float2(acc[mt][nt2][2], acc[mt][nt2][3]);
            }
        }

        grid_barrier_next(bar_tgt);   // partials visible

        // ---- fused activation: gates = xg + bias + sum of 8 partials ----
        {
            const float* pb = g_part + (size_t)bown * NGATE;

            float gv[4][2];
#pragma unroll
            for (int gi = 0; gi < 4; gi++) {
                int n = (gi << 10) | hc2;
                float sx = xv[gi].x, sy = xv[gi].y;
#pragma unroll
                for (int s = 0; s < NSPLIT; s++) {
                    float2 q = *(const float2*)(pb + (size_t)s * (BB * NGATE) + n);
                    sx += q.x; sy += q.y;
                }
                gv[gi][0] = sx; gv[gi][1] = sy;
            }
            gv[0][0] += bb0.x; gv[0][1] += bb0.y;
            gv[1][0] += bb1.x; gv[1][1] += bb1.y;
            gv[2][0] += bb2.x; gv[2][1] += bb2.y;
            gv[3][0] += bb3.x; gv[3][1] += bb3.y;

            float hv[2];
            float* cr = (float*)&creg;
#pragma unroll
            for (int e = 0; e < 2; e++) {
                float ig = 1.f / (1.f + expf(-gv[0][e]));
                float fg = 1.f / (1.f + expf(-gv[1][e]));
                float og = 1.f / (1.f + expf(-gv[2][e]));
                float ug = tanhf(gv[3][e]);
                float c = fg * cr[e] + ig * ug;
                cr[e] = c;
                hv[e] = og * tanhf(c);
            }
            if (t == TT - 1) {
                *(float2*)(out + bown * HH + hc2) = make_float2(hv[0], hv[1]);
            } else {
                *(uint2*)(g_h + bown * HH + hc2) =
                    make_uint2(f2tf32(hv[0]), f2tf32(hv[1]));
            }
        }

        grid_barrier_next(bar_tgt);   // h visible before next GEMM
    }
}

// ---------------------------------------------------------------------------
// Launch. Inputs: x[128,512,1024], adjacency (unused), Wx[4,1024,1024],
// Wh[4,1024,1024], b[4,1024]. Output: h [128,1024] f32.
// ---------------------------------------------------------------------------
extern "C" void kernel_launch(void* const* d_in, const int* in_sizes, int n_in,
                              void* d_out, int out_size)
{
    const float* x    = (const float*)d_in[0];
    const float* Wx   = (const float*)d_in[2];
    const float* Wh   = (const float*)d_in[3];
    const float* bias = (const float*)d_in[4];
    float* out = (float*)d_out;

    float *xg;
    uint32_t *xtf, *wxtf, *whtf;
    cudaGetSymbolAddress((void**)&xg,   g_xg);
    cudaGetSymbolAddress((void**)&xtf,  g_xtf);
    cudaGetSymbolAddress((void**)&wxtf, g_wxtf);
    cudaGetSymbolAddress((void**)&whtf, g_whtf);

    const int xg_smem  = (3 * XGA + 3 * XGB) * 4;           // 156672 B
    const int rec_smem = (128 * LDN + 3 * RCA) * 4;         // 190464 B
    static int configured = 0;
    if (!configured) {
        cudaFuncSetAttribute(gemm_xgates,
                             cudaFuncAttributeMaxDynamicSharedMemorySize, xg_smem);
        cudaFuncSetAttribute(lstm_recurrence,
                             cudaFuncAttributeMaxDynamicSharedMemorySize, rec_smem);
        configured = 1;
    }

    const int nx4 = BB * TT * DD / 4;
    const int nw4 = 4 * DD * HH / 4;
    cvt_tf32_arr<<<(nx4 + 255) / 256, 256>>>((const float4*)x,  (uint4*)xtf,  nx4);
    cvt_tf32_arr<<<(nw4 + 255) / 256, 256>>>((const float4*)Wx, (uint4*)wxtf, nw4);
    cvt_tf32_arr<<<(nw4 + 255) / 256, 256>>>((const float4*)Wh, (uint4*)whtf, nw4);

    gemm_xgates<<<dim3(16, 512), 512, xg_smem>>>(xg);
    lstm_recurrence<<<NCTA, 512, rec_smem>>>(xg, bias, out);
}